// round 13
// baseline (speedup 1.0000x reference)
#include <cuda_runtime.h>
#include <cstdint>

// Problem constants: B=8, H=16, S=1024, D=64.
#define Bb 8
#define Hh 16
#define Ss 1024
#define Dd 64

struct K2 { uint32_t a, b; };

__host__ __device__ constexpr uint32_t rotl_c(uint32_t x, int r) {
    return (x << r) | (x >> (32 - r));
}

constexpr K2 threefry_host(uint32_t k0, uint32_t k1, uint32_t c0, uint32_t c1) {
    uint32_t ks[3] = { k0, k1, 0x1BD11BDAu ^ k0 ^ k1 };
    uint32_t x0 = c0 + ks[0], x1 = c1 + ks[1];
    const int rot[8] = {13, 15, 26, 6, 17, 29, 16, 24};
    for (int g = 0; g < 5; ++g) {
        for (int i = 0; i < 4; ++i) {
            x0 += x1;
            x1 = rotl_c(x1, rot[(g & 1) * 4 + i]);
            x1 ^= x0;
        }
        x0 += ks[(g + 1) % 3];
        x1 += ks[(g + 2) % 3] + (uint32_t)(g + 1);
    }
    return { x0, x1 };
}

// JAX partitionable threefry: counter (0, idx), bits = x0 ^ x1
__device__ __forceinline__ uint32_t jax_bits(uint32_t idx, uint32_t k0, uint32_t k1) {
    const uint32_t ks2 = 0x1BD11BDAu ^ k0 ^ k1;
    uint32_t x0 = k0;
    uint32_t x1 = idx + k1;
#define TF_RND(r) { x0 += x1; x1 = __funnelshift_l(x1, x1, (r)); x1 ^= x0; }
    TF_RND(13) TF_RND(15) TF_RND(26) TF_RND(6)   x0 += k1;  x1 += ks2 + 1u;
    TF_RND(17) TF_RND(29) TF_RND(16) TF_RND(24)  x0 += ks2; x1 += k0 + 2u;
    TF_RND(13) TF_RND(15) TF_RND(26) TF_RND(6)   x0 += k0;  x1 += k1 + 3u;
    TF_RND(17) TF_RND(29) TF_RND(16) TF_RND(24)  x0 += k1;  x1 += ks2 + 4u;
    TF_RND(13) TF_RND(15) TF_RND(26) TF_RND(6)   x0 += ks2; x1 += k0 + 5u;
#undef TF_RND
    return x0 ^ x1;
}
// keep iff uniform(bits) < 0.9f  ⟺  bits < 0xE6666600
#define KEEP_THRESH 0xE6666600u

__device__ __forceinline__ uint32_t f2tf(float x) {
    uint32_t r;
    asm("cvt.rna.tf32.f32 %0, %1;" : "=r"(r) : "f"(x));
    return r;
}

#define MMA_TF32(d0,d1,d2,d3,a0,a1,a2,a3,b0,b1)                               \
    asm volatile("mma.sync.aligned.m16n8k8.row.col.f32.tf32.tf32.f32 "        \
                 "{%0,%1,%2,%3},{%4,%5,%6,%7},{%8,%9},{%0,%1,%2,%3};"         \
                 : "+f"(d0), "+f"(d1), "+f"(d2), "+f"(d3)                     \
                 : "r"(a0), "r"(a1), "r"(a2), "r"(a3), "r"(b0), "r"(b1))

// per-row exp-sum partials: [B*H*S rows][32 col-blocks of 32]
__device__ float g_rowsum[(size_t)Bb * Hh * Ss * 32];

// ============================================================================
// K_A: a = (mask && keep) ? exp((Q K^T)/8) : 0 -> Attn, + exp-sum partials
//      (rsum uses pre-dropout e).  Threefry interleaved INSIDE the MMA
//      mainloop: iteration ks computes the 4 keep-bits of (mt=ks>>2, nt=ks&3).
// CTA tile: 128 q-rows x 64 keys. grid (kt=16, qt=8, bh=128).
// ============================================================================
#define QKS 68
#define QK_SMEM_BYTES ((128 * QKS + 2 * 64 * QKS) * 4)

extern "C" __global__ void __launch_bounds__(256, 3)
qk_kernel(const float* __restrict__ Q, const float* __restrict__ K,
          const int* __restrict__ M, float* __restrict__ Attn,
          uint32_t rk0, uint32_t rk1)
{
    extern __shared__ float sm[];
    float*    sQ  = sm;
    uint32_t* sKh = (uint32_t*)(sm + 128 * QKS);
    float*    sKl = (float*)(sKh + 64 * QKS);

    const int kt = blockIdx.x, qt = blockIdx.y, bh = blockIdx.z;
    const int b  = bh >> 4;
    const int tid = threadIdx.x;
    const int w = tid >> 5, lane = tid & 31, g = lane >> 2, tig = lane & 3;

    const float* Qg = Q + ((size_t)bh * Ss + qt * 128) * Dd;
    const float* Kg = K + ((size_t)bh * Ss + kt * 64) * Dd;

    for (int i = tid; i < 128 * 16; i += 256) {
        int row = i >> 4, c4 = (i & 15) * 4;
        float4 v = ((const float4*)Qg)[i];
        float* p = sQ + row * QKS + c4;
        p[0] = v.x * 0.125f; p[1] = v.y * 0.125f;
        p[2] = v.z * 0.125f; p[3] = v.w * 0.125f;
    }
    for (int i = tid; i < 64 * 16; i += 256) {
        int row = i >> 4, c4 = (i & 15) * 4;
        float4 v = ((const float4*)Kg)[i];
        uint32_t* ph = sKh + row * QKS + c4;
        float*    pl = sKl + row * QKS + c4;
        uint32_t h0 = f2tf(v.x), h1 = f2tf(v.y), h2 = f2tf(v.z), h3 = f2tf(v.w);
        ph[0] = h0; ph[1] = h1; ph[2] = h2; ph[3] = h3;
        pl[0] = v.x - __uint_as_float(h0); pl[1] = v.y - __uint_as_float(h1);
        pl[2] = v.z - __uint_as_float(h2); pl[3] = v.w - __uint_as_float(h3);
    }
    __syncthreads();

    const int mblk = (w & 3) * 32;
    const int nblk = (w >> 2) * 32;

    // dropout index base for this thread's C elements:
    // element (mt, nt, jj):  idx = ibase + mt*(16<<10) + (jj>=2)*(8<<10)
    //                              + nt*8 + (jj&1)
    const uint32_t ibase =
        ((uint32_t)(bh * Ss + qt * 128 + mblk + g) << 10)
        + (uint32_t)(kt * 64 + nblk + tig * 2);
    uint32_t keepmask = 0;

    float acc[2][4][4];
    #pragma unroll
    for (int mt = 0; mt < 2; ++mt)
        #pragma unroll
        for (int nt = 0; nt < 4; ++nt)
            #pragma unroll
            for (int j = 0; j < 4; ++j) acc[mt][nt][j] = 0.f;

    #pragma unroll
    for (int ks = 0; ks < 8; ++ks) {
        // ---- threefry: 4 independent chains for (mt=ks>>2, nt=ks&3) ----
        {
            const int tmt = ks >> 2, tnt = ks & 3;
            const uint32_t e0 = ibase + (uint32_t)(tmt * (16 << 10) + tnt * 8);
            uint32_t b0 = jax_bits(e0,               rk0, rk1);
            uint32_t b1 = jax_bits(e0 + 1,           rk0, rk1);
            uint32_t b2 = jax_bits(e0 + (8 << 10),   rk0, rk1);
            uint32_t b3 = jax_bits(e0 + (8 << 10)+1, rk0, rk1);
            const int tb = tmt * 16 + tnt * 4;
            keepmask |= ((uint32_t)(b0 < KEEP_THRESH)) << (tb + 0);
            keepmask |= ((uint32_t)(b1 < KEEP_THRESH)) << (tb + 1);
            keepmask |= ((uint32_t)(b2 < KEEP_THRESH)) << (tb + 2);
            keepmask |= ((uint32_t)(b3 < KEEP_THRESH)) << (tb + 3);
        }

        // ---- MMA block ----
        uint32_t Ah[2][4], Al[2][4];
        #pragma unroll
        for (int mt = 0; mt < 2; ++mt) {
            const int r = mblk + mt * 16;
            const int c = ks * 8 + tig;
            float v0 = sQ[(r + g) * QKS + c];
            float v1 = sQ[(r + g + 8) * QKS + c];
            float v2 = sQ[(r + g) * QKS + c + 4];
            float v3 = sQ[(r + g + 8) * QKS + c + 4];
            Ah[mt][0] = f2tf(v0); Al[mt][0] = __float_as_uint(v0 - __uint_as_float(Ah[mt][0]));
            Ah[mt][1] = f2tf(v1); Al[mt][1] = __float_as_uint(v1 - __uint_as_float(Ah[mt][1]));
            Ah[mt][2] = f2tf(v2); Al[mt][2] = __float_as_uint(v2 - __uint_as_float(Ah[mt][2]));
            Ah[mt][3] = f2tf(v3); Al[mt][3] = __float_as_uint(v3 - __uint_as_float(Ah[mt][3]));
        }
        #pragma unroll
        for (int nt = 0; nt < 4; ++nt) {
            const int n = nblk + nt * 8 + g;
            const int c = ks * 8 + tig;
            uint32_t bh0 = sKh[n * QKS + c];
            uint32_t bh1 = sKh[n * QKS + c + 4];
            uint32_t bl0 = __float_as_uint(sKl[n * QKS + c]);
            uint32_t bl1 = __float_as_uint(sKl[n * QKS + c + 4]);
            #pragma unroll
            for (int mt = 0; mt < 2; ++mt) {
                MMA_TF32(acc[mt][nt][0],acc[mt][nt][1],acc[mt][nt][2],acc[mt][nt][3],
                         Ah[mt][0],Ah[mt][1],Ah[mt][2],Ah[mt][3], bh0,bh1);
                MMA_TF32(acc[mt][nt][0],acc[mt][nt][1],acc[mt][nt][2],acc[mt][nt][3],
                         Ah[mt][0],Ah[mt][1],Ah[mt][2],Ah[mt][3], bl0,bl1);
                MMA_TF32(acc[mt][nt][0],acc[mt][nt][1],acc[mt][nt][2],acc[mt][nt][3],
                         Al[mt][0],Al[mt][1],Al[mt][2],Al[mt][3], bh0,bh1);
            }
        }
    }

    // epilogue: e = mask ? exp(s) : 0 ; rsum += e ; a = keep ? e : 0 ; store a
    float rsum[2][2] = {{0.f, 0.f}, {0.f, 0.f}};
    #pragma unroll
    for (int mt = 0; mt < 2; ++mt) {
        #pragma unroll
        for (int nt = 0; nt < 4; ++nt) {
            const int gr0 = qt * 128 + mblk + mt * 16 + g;
            const int gr1 = gr0 + 8;
            const int gc  = kt * 64 + nblk + nt * 8 + tig * 2;
            int2 m0 = *(const int2*)(M + ((size_t)b * Ss + gr0) * Ss + gc);
            int2 m1 = *(const int2*)(M + ((size_t)b * Ss + gr1) * Ss + gc);
            float e00 = m0.x ? __expf(acc[mt][nt][0]) : 0.f;
            float e01 = m0.y ? __expf(acc[mt][nt][1]) : 0.f;
            float e10 = m1.x ? __expf(acc[mt][nt][2]) : 0.f;
            float e11 = m1.y ? __expf(acc[mt][nt][3]) : 0.f;
            rsum[mt][0] += e00 + e01;
            rsum[mt][1] += e10 + e11;
            const int tb = mt * 16 + nt * 4;
            float a00 = (keepmask >> (tb + 0)) & 1u ? e00 : 0.f;
            float a01 = (keepmask >> (tb + 1)) & 1u ? e01 : 0.f;
            float a10 = (keepmask >> (tb + 2)) & 1u ? e10 : 0.f;
            float a11 = (keepmask >> (tb + 3)) & 1u ? e11 : 0.f;
            *(float2*)(Attn + ((size_t)bh * Ss + gr0) * Ss + gc) = make_float2(a00, a01);
            *(float2*)(Attn + ((size_t)bh * Ss + gr1) * Ss + gc) = make_float2(a10, a11);
        }
    }
    const int cidx = kt * 2 + (nblk >> 5);
    #pragma unroll
    for (int mt = 0; mt < 2; ++mt) {
        float a = rsum[mt][0];
        a += __shfl_xor_sync(0xffffffffu, a, 1);
        a += __shfl_xor_sync(0xffffffffu, a, 2);
        float c = rsum[mt][1];
        c += __shfl_xor_sync(0xffffffffu, c, 1);
        c += __shfl_xor_sync(0xffffffffu, c, 2);
        if (tig == 0) {
            const uint32_t r0 = (uint32_t)(bh * Ss + qt * 128 + mblk + mt * 16 + g);
            g_rowsum[(size_t)r0 * 32 + cidx]       = a;
            g_rowsum[(size_t)(r0 + 8) * 32 + cidx] = c;
        }
    }
}

// ============================================================================
// K_B: normalize (a -> final weights) + PV.  NO threefry here.
// CTA: 128 q-rows x 64 d out. grid (qt=8, bh=128).  (R8 structure)
// ============================================================================
#define PVS 68
#define PVV 72
#define PV_SMEM_FLOATS (128 * PVS + 2 * 64 * PVV + 128)
#define PV_SMEM_BYTES (PV_SMEM_FLOATS * 4)

extern "C" __global__ void __launch_bounds__(256)
pv_kernel(float* __restrict__ Attn, const float* __restrict__ V,
          float* __restrict__ Out)
{
    extern __shared__ float sm[];
    float*    sP   = sm;                                   // 128*68
    uint32_t* sVh  = (uint32_t*)(sm + 128 * PVS);          // 64*72
    float*    sVl  = (float*)(sVh + 64 * PVV);             // 64*72
    float*    sInv = sVl + 64 * PVV;                       // 128

    const int qt = blockIdx.x, bh = blockIdx.y;
    const int tid = threadIdx.x;
    const int w = tid >> 5, lane = tid & 31, g = lane >> 2, tig = lane & 3;

    float* Ag = Attn + ((size_t)bh * Ss + qt * 128) * Ss;
    const float* Vg = V + (size_t)bh * Ss * Dd;

    // deterministic row-sum reduction from qk partials
    if (tid < 128) {
        const float4* p = (const float4*)(g_rowsum +
            ((size_t)(bh * Ss + qt * 128 + tid)) * 32);
        float s = 0.f;
        #pragma unroll
        for (int jj = 0; jj < 8; ++jj) {
            float4 v = p[jj];
            s += (v.x + v.y) + (v.z + v.w);
        }
        sInv[tid] = (1.0f / 0.9f) / s;
    }

    float acc[8][4];
    #pragma unroll
    for (int nt = 0; nt < 8; ++nt)
        #pragma unroll
        for (int jj = 0; jj < 4; ++jj) acc[nt][jj] = 0.f;

    for (int kt = 0; kt < 16; ++kt) {
        __syncthreads();
        // load a tile -> w = a*inv -> attn gmem (final weights) + sP
        for (int i = tid; i < 128 * 16; i += 256) {
            int row = i >> 4, c4 = (i & 15) * 4;
            float* gp = Ag + (size_t)row * Ss + kt * 64 + c4;
            float4 v = *(const float4*)gp;
            const float inv = sInv[row];
            v.x *= inv; v.y *= inv; v.z *= inv; v.w *= inv;
            *(float4*)gp = v;
            float* p = sP + row * PVS + c4;
            p[0] = v.x; p[1] = v.y; p[2] = v.z; p[3] = v.w;
        }
        // load V tile, hi/lo presplit
        for (int i = tid; i < 64 * 16; i += 256) {
            int row = i >> 4, c4 = (i & 15) * 4;
            float4 v = ((const float4*)(Vg + (size_t)(kt * 64 + row) * Dd))[(i & 15)];
            uint32_t* ph = sVh + row * PVV + c4;
            float*    pl = sVl + row * PVV + c4;
            uint32_t h0 = f2tf(v.x), h1 = f2tf(v.y), h2 = f2tf(v.z), h3 = f2tf(v.w);
            ph[0] = h0; ph[1] = h1; ph[2] = h2; ph[3] = h3;
            pl[0] = v.x - __uint_as_float(h0); pl[1] = v.y - __uint_as_float(h1);
            pl[2] = v.z - __uint_as_float(h2); pl[3] = v.w - __uint_as_float(h3);
        }
        __syncthreads();

        #pragma unroll
        for (int ks = 0; ks < 8; ++ks) {
            const int c = ks * 8 + tig;
            float v0 = sP[(w * 16 + g) * PVS + c];
            float v1 = sP[(w * 16 + g + 8) * PVS + c];
            float v2 = sP[(w * 16 + g) * PVS + c + 4];
            float v3 = sP[(w * 16 + g + 8) * PVS + c + 4];
            uint32_t A0h = f2tf(v0), A1h = f2tf(v1), A2h = f2tf(v2), A3h = f2tf(v3);
            uint32_t A0l = __float_as_uint(v0 - __uint_as_float(A0h));
            uint32_t A1l = __float_as_uint(v1 - __uint_as_float(A1h));
            uint32_t A2l = __float_as_uint(v2 - __uint_as_float(A2h));
            uint32_t A3l = __float_as_uint(v3 - __uint_as_float(A3h));

            #pragma unroll
            for (int nt = 0; nt < 8; ++nt) {
                const int col = nt * 8 + g;
                uint32_t bh0 = sVh[(ks * 8 + tig) * PVV + col];
                uint32_t bh1 = sVh[(ks * 8 + tig + 4) * PVV + col];
                uint32_t bl0 = __float_as_uint(sVl[(ks * 8 + tig) * PVV + col]);
                uint32_t bl1 = __float_as_uint(sVl[(ks * 8 + tig + 4) * PVV + col]);
                MMA_TF32(acc[nt][0],acc[nt][1],acc[nt][2],acc[nt][3],
                         A0h,A1h,A2h,A3h, bh0,bh1);
                MMA_TF32(acc[nt][0],acc[nt][1],acc[nt][2],acc[nt][3],
                         A0h,A1h,A2h,A3h, bl0,bl1);
                MMA_TF32(acc[nt][0],acc[nt][1],acc[nt][2],acc[nt][3],
                         A0l,A1l,A2l,A3l, bh0,bh1);
            }
        }
    }

    const int gr0 = qt * 128 + w * 16 + g;
    const int gr1 = gr0 + 8;
    float* Ob = Out + (size_t)bh * Ss * Dd;
    #pragma unroll
    for (int nt = 0; nt < 8; ++nt) {
        const int col = nt * 8 + tig * 2;
        *(float2*)(Ob + (size_t)gr0 * Dd + col) = make_float2(acc[nt][0], acc[nt][1]);
        *(float2*)(Ob + (size_t)gr1 * Dd + col) = make_float2(acc[nt][2], acc[nt][3]);
    }
}

// ============================================================================
extern "C" void kernel_launch(void* const* d_in, const int* in_sizes, int n_in,
                              void* d_out, int out_size) {
    const float* Q = (const float*)d_in[0];
    const float* K = (const float*)d_in[1];
    const float* V = (const float*)d_in[2];
    const int*   M = (const int*)d_in[3];

    float* out  = (float*)d_out;
    float* attn = out + (size_t)Bb * Hh * Ss * Dd;

    constexpr K2 DK = threefry_host(0u, 42u, 0u, 7u);

    cudaFuncSetAttribute(qk_kernel, cudaFuncAttributeMaxDynamicSharedMemorySize,
                         QK_SMEM_BYTES);
    cudaFuncSetAttribute(pv_kernel, cudaFuncAttributeMaxDynamicSharedMemorySize,
                         PV_SMEM_BYTES);

    qk_kernel<<<dim3(16, 8, 128), 256, QK_SMEM_BYTES>>>(Q, K, M, attn, DK.a, DK.b);
    pv_kernel<<<dim3(8, 128), 256, PV_SMEM_BYTES>>>(attn, V, out);
}

// round 14
// speedup vs baseline: 1.0009x; 1.0009x over previous
#include <cuda_runtime.h>
#include <cstdint>

// Problem constants: B=8, H=16, S=1024, D=64.
#define Bb 8
#define Hh 16
#define Ss 1024
#define Dd 64

struct K2 { uint32_t a, b; };

__host__ __device__ constexpr uint32_t rotl_c(uint32_t x, int r) {
    return (x << r) | (x >> (32 - r));
}

constexpr K2 threefry_host(uint32_t k0, uint32_t k1, uint32_t c0, uint32_t c1) {
    uint32_t ks[3] = { k0, k1, 0x1BD11BDAu ^ k0 ^ k1 };
    uint32_t x0 = c0 + ks[0], x1 = c1 + ks[1];
    const int rot[8] = {13, 15, 26, 6, 17, 29, 16, 24};
    for (int g = 0; g < 5; ++g) {
        for (int i = 0; i < 4; ++i) {
            x0 += x1;
            x1 = rotl_c(x1, rot[(g & 1) * 4 + i]);
            x1 ^= x0;
        }
        x0 += ks[(g + 1) % 3];
        x1 += ks[(g + 2) % 3] + (uint32_t)(g + 1);
    }
    return { x0, x1 };
}

// JAX partitionable threefry: counter (0, idx), bits = x0 ^ x1
__device__ __forceinline__ uint32_t jax_bits(uint32_t idx, uint32_t k0, uint32_t k1) {
    const uint32_t ks2 = 0x1BD11BDAu ^ k0 ^ k1;
    uint32_t x0 = k0;
    uint32_t x1 = idx + k1;
#define TF_RND(r) { x0 += x1; x1 = __funnelshift_l(x1, x1, (r)); x1 ^= x0; }
    TF_RND(13) TF_RND(15) TF_RND(26) TF_RND(6)   x0 += k1;  x1 += ks2 + 1u;
    TF_RND(17) TF_RND(29) TF_RND(16) TF_RND(24)  x0 += ks2; x1 += k0 + 2u;
    TF_RND(13) TF_RND(15) TF_RND(26) TF_RND(6)   x0 += k0;  x1 += k1 + 3u;
    TF_RND(17) TF_RND(29) TF_RND(16) TF_RND(24)  x0 += k1;  x1 += ks2 + 4u;
    TF_RND(13) TF_RND(15) TF_RND(26) TF_RND(6)   x0 += ks2; x1 += k0 + 5u;
#undef TF_RND
    return x0 ^ x1;
}
// keep iff uniform(bits) < 0.9f  ⟺  bits < 0xE6666600
#define KEEP_THRESH 0xE6666600u

__device__ __forceinline__ uint32_t f2tf(float x) {
    uint32_t r;
    asm("cvt.rna.tf32.f32 %0, %1;" : "=r"(r) : "f"(x));
    return r;
}

#define MMA_TF32(d0,d1,d2,d3,a0,a1,a2,a3,b0,b1)                               \
    asm volatile("mma.sync.aligned.m16n8k8.row.col.f32.tf32.tf32.f32 "        \
                 "{%0,%1,%2,%3},{%4,%5,%6,%7},{%8,%9},{%0,%1,%2,%3};"         \
                 : "+f"(d0), "+f"(d1), "+f"(d2), "+f"(d3)                     \
                 : "r"(a0), "r"(a1), "r"(a2), "r"(a3), "r"(b0), "r"(b1))

// per-row exp-sum partials: [B*H*S rows][32 col-blocks of 32]
__device__ float g_rowsum[(size_t)Bb * Hh * Ss * 32];

// ============================================================================
// K_A: a = (mask && keep) ? exp((Q K^T)/8) : 0 -> Attn, + exp-sum partials
//      (rsum uses pre-dropout e).  Threefry interleaved INSIDE the MMA
//      mainloop: iteration ks computes the 4 keep-bits of (mt=ks>>2, nt=ks&3).
// CTA tile: 128 q-rows x 64 keys. grid (kt=16, qt=8, bh=128).
// ============================================================================
#define QKS 68
#define QK_SMEM_BYTES ((128 * QKS + 2 * 64 * QKS) * 4)

extern "C" __global__ void __launch_bounds__(256, 3)
qk_kernel(const float* __restrict__ Q, const float* __restrict__ K,
          const int* __restrict__ M, float* __restrict__ Attn,
          uint32_t rk0, uint32_t rk1)
{
    extern __shared__ float sm[];
    float*    sQ  = sm;
    uint32_t* sKh = (uint32_t*)(sm + 128 * QKS);
    float*    sKl = (float*)(sKh + 64 * QKS);

    const int kt = blockIdx.x, qt = blockIdx.y, bh = blockIdx.z;
    const int b  = bh >> 4;
    const int tid = threadIdx.x;
    const int w = tid >> 5, lane = tid & 31, g = lane >> 2, tig = lane & 3;

    const float* Qg = Q + ((size_t)bh * Ss + qt * 128) * Dd;
    const float* Kg = K + ((size_t)bh * Ss + kt * 64) * Dd;

    for (int i = tid; i < 128 * 16; i += 256) {
        int row = i >> 4, c4 = (i & 15) * 4;
        float4 v = ((const float4*)Qg)[i];
        float* p = sQ + row * QKS + c4;
        p[0] = v.x * 0.125f; p[1] = v.y * 0.125f;
        p[2] = v.z * 0.125f; p[3] = v.w * 0.125f;
    }
    for (int i = tid; i < 64 * 16; i += 256) {
        int row = i >> 4, c4 = (i & 15) * 4;
        float4 v = ((const float4*)Kg)[i];
        uint32_t* ph = sKh + row * QKS + c4;
        float*    pl = sKl + row * QKS + c4;
        uint32_t h0 = f2tf(v.x), h1 = f2tf(v.y), h2 = f2tf(v.z), h3 = f2tf(v.w);
        ph[0] = h0; ph[1] = h1; ph[2] = h2; ph[3] = h3;
        pl[0] = v.x - __uint_as_float(h0); pl[1] = v.y - __uint_as_float(h1);
        pl[2] = v.z - __uint_as_float(h2); pl[3] = v.w - __uint_as_float(h3);
    }
    __syncthreads();

    const int mblk = (w & 3) * 32;
    const int nblk = (w >> 2) * 32;

    // dropout index base for this thread's C elements:
    // element (mt, nt, jj):  idx = ibase + mt*(16<<10) + (jj>=2)*(8<<10)
    //                              + nt*8 + (jj&1)
    const uint32_t ibase =
        ((uint32_t)(bh * Ss + qt * 128 + mblk + g) << 10)
        + (uint32_t)(kt * 64 + nblk + tig * 2);
    uint32_t keepmask = 0;

    float acc[2][4][4];
    #pragma unroll
    for (int mt = 0; mt < 2; ++mt)
        #pragma unroll
        for (int nt = 0; nt < 4; ++nt)
            #pragma unroll
            for (int j = 0; j < 4; ++j) acc[mt][nt][j] = 0.f;

    #pragma unroll
    for (int ks = 0; ks < 8; ++ks) {
        // ---- threefry: 4 independent chains for (mt=ks>>2, nt=ks&3) ----
        {
            const int tmt = ks >> 2, tnt = ks & 3;
            const uint32_t e0 = ibase + (uint32_t)(tmt * (16 << 10) + tnt * 8);
            uint32_t b0 = jax_bits(e0,               rk0, rk1);
            uint32_t b1 = jax_bits(e0 + 1,           rk0, rk1);
            uint32_t b2 = jax_bits(e0 + (8 << 10),   rk0, rk1);
            uint32_t b3 = jax_bits(e0 + (8 << 10)+1, rk0, rk1);
            const int tb = tmt * 16 + tnt * 4;
            keepmask |= ((uint32_t)(b0 < KEEP_THRESH)) << (tb + 0);
            keepmask |= ((uint32_t)(b1 < KEEP_THRESH)) << (tb + 1);
            keepmask |= ((uint32_t)(b2 < KEEP_THRESH)) << (tb + 2);
            keepmask |= ((uint32_t)(b3 < KEEP_THRESH)) << (tb + 3);
        }

        // ---- MMA block ----
        uint32_t Ah[2][4], Al[2][4];
        #pragma unroll
        for (int mt = 0; mt < 2; ++mt) {
            const int r = mblk + mt * 16;
            const int c = ks * 8 + tig;
            float v0 = sQ[(r + g) * QKS + c];
            float v1 = sQ[(r + g + 8) * QKS + c];
            float v2 = sQ[(r + g) * QKS + c + 4];
            float v3 = sQ[(r + g + 8) * QKS + c + 4];
            Ah[mt][0] = f2tf(v0); Al[mt][0] = __float_as_uint(v0 - __uint_as_float(Ah[mt][0]));
            Ah[mt][1] = f2tf(v1); Al[mt][1] = __float_as_uint(v1 - __uint_as_float(Ah[mt][1]));
            Ah[mt][2] = f2tf(v2); Al[mt][2] = __float_as_uint(v2 - __uint_as_float(Ah[mt][2]));
            Ah[mt][3] = f2tf(v3); Al[mt][3] = __float_as_uint(v3 - __uint_as_float(Ah[mt][3]));
        }
        #pragma unroll
        for (int nt = 0; nt < 4; ++nt) {
            const int n = nblk + nt * 8 + g;
            const int c = ks * 8 + tig;
            uint32_t bh0 = sKh[n * QKS + c];
            uint32_t bh1 = sKh[n * QKS + c + 4];
            uint32_t bl0 = __float_as_uint(sKl[n * QKS + c]);
            uint32_t bl1 = __float_as_uint(sKl[n * QKS + c + 4]);
            #pragma unroll
            for (int mt = 0; mt < 2; ++mt) {
                MMA_TF32(acc[mt][nt][0],acc[mt][nt][1],acc[mt][nt][2],acc[mt][nt][3],
                         Ah[mt][0],Ah[mt][1],Ah[mt][2],Ah[mt][3], bh0,bh1);
                MMA_TF32(acc[mt][nt][0],acc[mt][nt][1],acc[mt][nt][2],acc[mt][nt][3],
                         Ah[mt][0],Ah[mt][1],Ah[mt][2],Ah[mt][3], bl0,bl1);
                MMA_TF32(acc[mt][nt][0],acc[mt][nt][1],acc[mt][nt][2],acc[mt][nt][3],
                         Al[mt][0],Al[mt][1],Al[mt][2],Al[mt][3], bh0,bh1);
            }
        }
    }

    // epilogue: e = mask ? exp(s) : 0 ; rsum += e ; a = keep ? e : 0 ; store a
    float rsum[2][2] = {{0.f, 0.f}, {0.f, 0.f}};
    #pragma unroll
    for (int mt = 0; mt < 2; ++mt) {
        #pragma unroll
        for (int nt = 0; nt < 4; ++nt) {
            const int gr0 = qt * 128 + mblk + mt * 16 + g;
            const int gr1 = gr0 + 8;
            const int gc  = kt * 64 + nblk + nt * 8 + tig * 2;
            int2 m0 = *(const int2*)(M + ((size_t)b * Ss + gr0) * Ss + gc);
            int2 m1 = *(const int2*)(M + ((size_t)b * Ss + gr1) * Ss + gc);
            float e00 = m0.x ? __expf(acc[mt][nt][0]) : 0.f;
            float e01 = m0.y ? __expf(acc[mt][nt][1]) : 0.f;
            float e10 = m1.x ? __expf(acc[mt][nt][2]) : 0.f;
            float e11 = m1.y ? __expf(acc[mt][nt][3]) : 0.f;
            rsum[mt][0] += e00 + e01;
            rsum[mt][1] += e10 + e11;
            const int tb = mt * 16 + nt * 4;
            float a00 = (keepmask >> (tb + 0)) & 1u ? e00 : 0.f;
            float a01 = (keepmask >> (tb + 1)) & 1u ? e01 : 0.f;
            float a10 = (keepmask >> (tb + 2)) & 1u ? e10 : 0.f;
            float a11 = (keepmask >> (tb + 3)) & 1u ? e11 : 0.f;
            *(float2*)(Attn + ((size_t)bh * Ss + gr0) * Ss + gc) = make_float2(a00, a01);
            *(float2*)(Attn + ((size_t)bh * Ss + gr1) * Ss + gc) = make_float2(a10, a11);
        }
    }
    const int cidx = kt * 2 + (nblk >> 5);
    #pragma unroll
    for (int mt = 0; mt < 2; ++mt) {
        float a = rsum[mt][0];
        a += __shfl_xor_sync(0xffffffffu, a, 1);
        a += __shfl_xor_sync(0xffffffffu, a, 2);
        float c = rsum[mt][1];
        c += __shfl_xor_sync(0xffffffffu, c, 1);
        c += __shfl_xor_sync(0xffffffffu, c, 2);
        if (tig == 0) {
            const uint32_t r0 = (uint32_t)(bh * Ss + qt * 128 + mblk + mt * 16 + g);
            g_rowsum[(size_t)r0 * 32 + cidx]       = a;
            g_rowsum[(size_t)(r0 + 8) * 32 + cidx] = c;
        }
    }
}

// ============================================================================
// K_B: normalize (a -> final weights) + PV.  NO threefry here.
// CTA: 128 q-rows x 64 d out. grid (qt=8, bh=128).  (R8 structure)
// ============================================================================
#define PVS 68
#define PVV 72
#define PV_SMEM_FLOATS (128 * PVS + 2 * 64 * PVV + 128)
#define PV_SMEM_BYTES (PV_SMEM_FLOATS * 4)

extern "C" __global__ void __launch_bounds__(256)
pv_kernel(float* __restrict__ Attn, const float* __restrict__ V,
          float* __restrict__ Out)
{
    extern __shared__ float sm[];
    float*    sP   = sm;                                   // 128*68
    uint32_t* sVh  = (uint32_t*)(sm + 128 * PVS);          // 64*72
    float*    sVl  = (float*)(sVh + 64 * PVV);             // 64*72
    float*    sInv = sVl + 64 * PVV;                       // 128

    const int qt = blockIdx.x, bh = blockIdx.y;
    const int tid = threadIdx.x;
    const int w = tid >> 5, lane = tid & 31, g = lane >> 2, tig = lane & 3;

    float* Ag = Attn + ((size_t)bh * Ss + qt * 128) * Ss;
    const float* Vg = V + (size_t)bh * Ss * Dd;

    // deterministic row-sum reduction from qk partials
    if (tid < 128) {
        const float4* p = (const float4*)(g_rowsum +
            ((size_t)(bh * Ss + qt * 128 + tid)) * 32);
        float s = 0.f;
        #pragma unroll
        for (int jj = 0; jj < 8; ++jj) {
            float4 v = p[jj];
            s += (v.x + v.y) + (v.z + v.w);
        }
        sInv[tid] = (1.0f / 0.9f) / s;
    }

    float acc[8][4];
    #pragma unroll
    for (int nt = 0; nt < 8; ++nt)
        #pragma unroll
        for (int jj = 0; jj < 4; ++jj) acc[nt][jj] = 0.f;

    for (int kt = 0; kt < 16; ++kt) {
        __syncthreads();
        // load a tile -> w = a*inv -> attn gmem (final weights) + sP
        for (int i = tid; i < 128 * 16; i += 256) {
            int row = i >> 4, c4 = (i & 15) * 4;
            float* gp = Ag + (size_t)row * Ss + kt * 64 + c4;
            float4 v = *(const float4*)gp;
            const float inv = sInv[row];
            v.x *= inv; v.y *= inv; v.z *= inv; v.w *= inv;
            *(float4*)gp = v;
            float* p = sP + row * PVS + c4;
            p[0] = v.x; p[1] = v.y; p[2] = v.z; p[3] = v.w;
        }
        // load V tile, hi/lo presplit
        for (int i = tid; i < 64 * 16; i += 256) {
            int row = i >> 4, c4 = (i & 15) * 4;
            float4 v = ((const float4*)(Vg + (size_t)(kt * 64 + row) * Dd))[(i & 15)];
            uint32_t* ph = sVh + row * PVV + c4;
            float*    pl = sVl + row * PVV + c4;
            uint32_t h0 = f2tf(v.x), h1 = f2tf(v.y), h2 = f2tf(v.z), h3 = f2tf(v.w);
            ph[0] = h0; ph[1] = h1; ph[2] = h2; ph[3] = h3;
            pl[0] = v.x - __uint_as_float(h0); pl[1] = v.y - __uint_as_float(h1);
            pl[2] = v.z - __uint_as_float(h2); pl[3] = v.w - __uint_as_float(h3);
        }
        __syncthreads();

        #pragma unroll
        for (int ks = 0; ks < 8; ++ks) {
            const int c = ks * 8 + tig;
            float v0 = sP[(w * 16 + g) * PVS + c];
            float v1 = sP[(w * 16 + g + 8) * PVS + c];
            float v2 = sP[(w * 16 + g) * PVS + c + 4];
            float v3 = sP[(w * 16 + g + 8) * PVS + c + 4];
            uint32_t A0h = f2tf(v0), A1h = f2tf(v1), A2h = f2tf(v2), A3h = f2tf(v3);
            uint32_t A0l = __float_as_uint(v0 - __uint_as_float(A0h));
            uint32_t A1l = __float_as_uint(v1 - __uint_as_float(A1h));
            uint32_t A2l = __float_as_uint(v2 - __uint_as_float(A2h));
            uint32_t A3l = __float_as_uint(v3 - __uint_as_float(A3h));

            #pragma unroll
            for (int nt = 0; nt < 8; ++nt) {
                const int col = nt * 8 + g;
                uint32_t bh0 = sVh[(ks * 8 + tig) * PVV + col];
                uint32_t bh1 = sVh[(ks * 8 + tig + 4) * PVV + col];
                uint32_t bl0 = __float_as_uint(sVl[(ks * 8 + tig) * PVV + col]);
                uint32_t bl1 = __float_as_uint(sVl[(ks * 8 + tig + 4) * PVV + col]);
                MMA_TF32(acc[nt][0],acc[nt][1],acc[nt][2],acc[nt][3],
                         A0h,A1h,A2h,A3h, bh0,bh1);
                MMA_TF32(acc[nt][0],acc[nt][1],acc[nt][2],acc[nt][3],
                         A0h,A1h,A2h,A3h, bl0,bl1);
                MMA_TF32(acc[nt][0],acc[nt][1],acc[nt][2],acc[nt][3],
                         A0l,A1l,A2l,A3l, bh0,bh1);
            }
        }
    }

    const int gr0 = qt * 128 + w * 16 + g;
    const int gr1 = gr0 + 8;
    float* Ob = Out + (size_t)bh * Ss * Dd;
    #pragma unroll
    for (int nt = 0; nt < 8; ++nt) {
        const int col = nt * 8 + tig * 2;
        *(float2*)(Ob + (size_t)gr0 * Dd + col) = make_float2(acc[nt][0], acc[nt][1]);
        *(float2*)(Ob + (size_t)gr1 * Dd + col) = make_float2(acc[nt][2], acc[nt][3]);
    }
}

// ============================================================================
extern "C" void kernel_launch(void* const* d_in, const int* in_sizes, int n_in,
                              void* d_out, int out_size) {
    const float* Q = (const float*)d_in[0];
    const float* K = (const float*)d_in[1];
    const float* V = (const float*)d_in[2];
    const int*   M = (const int*)d_in[3];

    float* out  = (float*)d_out;
    float* attn = out + (size_t)Bb * Hh * Ss * Dd;

    constexpr K2 DK = threefry_host(0u, 42u, 0u, 7u);

    cudaFuncSetAttribute(qk_kernel, cudaFuncAttributeMaxDynamicSharedMemorySize,
                         QK_SMEM_BYTES);
    cudaFuncSetAttribute(pv_kernel, cudaFuncAttributeMaxDynamicSharedMemorySize,
                         PV_SMEM_BYTES);

    qk_kernel<<<dim3(16, 8, 128), 256, QK_SMEM_BYTES>>>(Q, K, M, attn, DK.a, DK.b);
    pv_kernel<<<dim3(8, 128), 256, PV_SMEM_BYTES>>>(attn, V, out);
}

// round 17
// speedup vs baseline: 1.1123x; 1.1113x over previous
#include <cuda_runtime.h>
#include <cstdint>

// Problem constants: B=8, H=16, S=1024, D=64.
#define Bb 8
#define Hh 16
#define Ss 1024
#define Dd 64

struct K2 { uint32_t a, b; };

__host__ __device__ constexpr uint32_t rotl_c(uint32_t x, int r) {
    return (x << r) | (x >> (32 - r));
}

constexpr K2 threefry_host(uint32_t k0, uint32_t k1, uint32_t c0, uint32_t c1) {
    uint32_t ks[3] = { k0, k1, 0x1BD11BDAu ^ k0 ^ k1 };
    uint32_t x0 = c0 + ks[0], x1 = c1 + ks[1];
    const int rot[8] = {13, 15, 26, 6, 17, 29, 16, 24};
    for (int g = 0; g < 5; ++g) {
        for (int i = 0; i < 4; ++i) {
            x0 += x1;
            x1 = rotl_c(x1, rot[(g & 1) * 4 + i]);
            x1 ^= x0;
        }
        x0 += ks[(g + 1) % 3];
        x1 += ks[(g + 2) % 3] + (uint32_t)(g + 1);
    }
    return { x0, x1 };
}

// JAX partitionable threefry: counter (0, idx), bits = x0 ^ x1
__device__ __forceinline__ uint32_t jax_bits(uint32_t idx, uint32_t k0, uint32_t k1) {
    const uint32_t ks2 = 0x1BD11BDAu ^ k0 ^ k1;
    uint32_t x0 = k0;
    uint32_t x1 = idx + k1;
#define TF_RND(r) { x0 += x1; x1 = __funnelshift_l(x1, x1, (r)); x1 ^= x0; }
    TF_RND(13) TF_RND(15) TF_RND(26) TF_RND(6)   x0 += k1;  x1 += ks2 + 1u;
    TF_RND(17) TF_RND(29) TF_RND(16) TF_RND(24)  x0 += ks2; x1 += k0 + 2u;
    TF_RND(13) TF_RND(15) TF_RND(26) TF_RND(6)   x0 += k0;  x1 += k1 + 3u;
    TF_RND(17) TF_RND(29) TF_RND(16) TF_RND(24)  x0 += k1;  x1 += ks2 + 4u;
    TF_RND(13) TF_RND(15) TF_RND(26) TF_RND(6)   x0 += ks2; x1 += k0 + 5u;
#undef TF_RND
    return x0 ^ x1;
}
// keep iff uniform(bits) < 0.9f  ⟺  bits < 0xE6666600
#define KEEP_THRESH 0xE6666600u

__device__ __forceinline__ uint32_t f2tf(float x) {
    uint32_t r;
    asm("cvt.rna.tf32.f32 %0, %1;" : "=r"(r) : "f"(x));
    return r;
}

#define MMA_TF32(d0,d1,d2,d3,a0,a1,a2,a3,b0,b1)                               \
    asm volatile("mma.sync.aligned.m16n8k8.row.col.f32.tf32.tf32.f32 "        \
                 "{%0,%1,%2,%3},{%4,%5,%6,%7},{%8,%9},{%0,%1,%2,%3};"         \
                 : "+f"(d0), "+f"(d1), "+f"(d2), "+f"(d3)                     \
                 : "r"(a0), "r"(a1), "r"(a2), "r"(a3), "r"(b0), "r"(b1))

// per-row exp-sum partials: [B*H*S rows][16 kt tiles]
__device__ float g_rowsum[(size_t)Bb * Hh * Ss * 16];

// ============================================================================
// K_A: e = mask ? exp((Q K^T)/8) : 0  -> Attn buffer, + per-kt exp-sums.
// Epilogue now COALESCED: fragments staged to smem, then coop float4 pass.
// CTA tile: 128 q-rows x 64 keys. grid (kt=16, qt=8, bh=128).
// ============================================================================
#define QKS 68
#define QK_SMEM_BYTES ((128 * QKS + 2 * 64 * QKS) * 4)

extern "C" __global__ void __launch_bounds__(256, 3)
qk_kernel(const float* __restrict__ Q, const float* __restrict__ K,
          const int* __restrict__ M, float* __restrict__ Attn)
{
    extern __shared__ float sm[];
    float*    sQ  = sm;                                   // 128*68
    uint32_t* sKh = (uint32_t*)(sm + 128 * QKS);          // 64*68
    float*    sKl = (float*)(sKh + 64 * QKS);             // 64*68
    float*    sS  = (float*)sKh;                          // 128*68 (reuse after mainloop)

    const int kt = blockIdx.x, qt = blockIdx.y, bh = blockIdx.z;
    const int b  = bh >> 4;
    const int tid = threadIdx.x;
    const int w = tid >> 5, lane = tid & 31, g = lane >> 2, tig = lane & 3;

    const float* Qg = Q + ((size_t)bh * Ss + qt * 128) * Dd;
    const float* Kg = K + ((size_t)bh * Ss + kt * 64) * Dd;

    for (int i = tid; i < 128 * 16; i += 256) {
        int row = i >> 4, c4 = (i & 15) * 4;
        float4 v = ((const float4*)Qg)[i];
        float* p = sQ + row * QKS + c4;
        p[0] = v.x * 0.125f; p[1] = v.y * 0.125f;
        p[2] = v.z * 0.125f; p[3] = v.w * 0.125f;
    }
    for (int i = tid; i < 64 * 16; i += 256) {
        int row = i >> 4, c4 = (i & 15) * 4;
        float4 v = ((const float4*)Kg)[i];
        uint32_t* ph = sKh + row * QKS + c4;
        float*    pl = sKl + row * QKS + c4;
        uint32_t h0 = f2tf(v.x), h1 = f2tf(v.y), h2 = f2tf(v.z), h3 = f2tf(v.w);
        ph[0] = h0; ph[1] = h1; ph[2] = h2; ph[3] = h3;
        pl[0] = v.x - __uint_as_float(h0); pl[1] = v.y - __uint_as_float(h1);
        pl[2] = v.z - __uint_as_float(h2); pl[3] = v.w - __uint_as_float(h3);
    }
    __syncthreads();

    const int mblk = (w & 3) * 32;
    const int nblk = (w >> 2) * 32;

    float acc[2][4][4];
    #pragma unroll
    for (int mt = 0; mt < 2; ++mt)
        #pragma unroll
        for (int nt = 0; nt < 4; ++nt)
            #pragma unroll
            for (int j = 0; j < 4; ++j) acc[mt][nt][j] = 0.f;

    #pragma unroll
    for (int ks = 0; ks < 8; ++ks) {
        uint32_t Ah[2][4], Al[2][4];
        #pragma unroll
        for (int mt = 0; mt < 2; ++mt) {
            const int r = mblk + mt * 16;
            const int c = ks * 8 + tig;
            float v0 = sQ[(r + g) * QKS + c];
            float v1 = sQ[(r + g + 8) * QKS + c];
            float v2 = sQ[(r + g) * QKS + c + 4];
            float v3 = sQ[(r + g + 8) * QKS + c + 4];
            Ah[mt][0] = f2tf(v0); Al[mt][0] = __float_as_uint(v0 - __uint_as_float(Ah[mt][0]));
            Ah[mt][1] = f2tf(v1); Al[mt][1] = __float_as_uint(v1 - __uint_as_float(Ah[mt][1]));
            Ah[mt][2] = f2tf(v2); Al[mt][2] = __float_as_uint(v2 - __uint_as_float(Ah[mt][2]));
            Ah[mt][3] = f2tf(v3); Al[mt][3] = __float_as_uint(v3 - __uint_as_float(Ah[mt][3]));
        }
        #pragma unroll
        for (int nt = 0; nt < 4; ++nt) {
            const int n = nblk + nt * 8 + g;
            const int c = ks * 8 + tig;
            uint32_t bh0 = sKh[n * QKS + c];
            uint32_t bh1 = sKh[n * QKS + c + 4];
            uint32_t bl0 = __float_as_uint(sKl[n * QKS + c]);
            uint32_t bl1 = __float_as_uint(sKl[n * QKS + c + 4]);
            #pragma unroll
            for (int mt = 0; mt < 2; ++mt) {
                MMA_TF32(acc[mt][nt][0],acc[mt][nt][1],acc[mt][nt][2],acc[mt][nt][3],
                         Ah[mt][0],Ah[mt][1],Ah[mt][2],Ah[mt][3], bh0,bh1);
                MMA_TF32(acc[mt][nt][0],acc[mt][nt][1],acc[mt][nt][2],acc[mt][nt][3],
                         Ah[mt][0],Ah[mt][1],Ah[mt][2],Ah[mt][3], bl0,bl1);
                MMA_TF32(acc[mt][nt][0],acc[mt][nt][1],acc[mt][nt][2],acc[mt][nt][3],
                         Al[mt][0],Al[mt][1],Al[mt][2],Al[mt][3], bh0,bh1);
            }
        }
    }

    // ---- stage raw scores to smem (K tile is dead now) ----
    __syncthreads();
    #pragma unroll
    for (int mt = 0; mt < 2; ++mt) {
        #pragma unroll
        for (int nt = 0; nt < 4; ++nt) {
            const int r0 = mblk + mt * 16 + g;
            const int r1 = r0 + 8;
            const int col = nblk + nt * 8 + tig * 2;
            *(float2*)(sS + r0 * QKS + col) = make_float2(acc[mt][nt][0], acc[mt][nt][1]);
            *(float2*)(sS + r1 * QKS + col) = make_float2(acc[mt][nt][2], acc[mt][nt][3]);
        }
    }
    __syncthreads();

    // ---- cooperative coalesced epilogue: mask -> exp -> rowsum -> store e ----
    // i = tid + 256*j : row = i>>4 (16 threads per row), c4 = (i&15)*4
    const int*   Mb = M    + ((size_t)b  * Ss + qt * 128) * Ss + kt * 64;
    float*       Ab = Attn + ((size_t)bh * Ss + qt * 128) * Ss + kt * 64;
    #pragma unroll
    for (int j = 0; j < 8; ++j) {
        const int i   = tid + 256 * j;
        const int row = i >> 4;
        const int c4  = (i & 15) * 4;
        int4 m = *(const int4*)(Mb + (size_t)row * Ss + c4);
        const float* sp = sS + row * QKS + c4;
        float e0 = m.x ? __expf(sp[0]) : 0.f;
        float e1 = m.y ? __expf(sp[1]) : 0.f;
        float e2 = m.z ? __expf(sp[2]) : 0.f;
        float e3 = m.w ? __expf(sp[3]) : 0.f;
        float part = (e0 + e1) + (e2 + e3);
        // reduce over the 16 threads that own this row (xor pattern stays
        // inside a 16-lane group, which is fully within one warp)
        part += __shfl_xor_sync(0xffffffffu, part, 1);
        part += __shfl_xor_sync(0xffffffffu, part, 2);
        part += __shfl_xor_sync(0xffffffffu, part, 4);
        part += __shfl_xor_sync(0xffffffffu, part, 8);
        if ((tid & 15) == 0)
            g_rowsum[(size_t)(bh * Ss + qt * 128 + row) * 16 + kt] = part;
        *(float4*)(Ab + (size_t)row * Ss + c4) = make_float4(e0, e1, e2, e3);
    }
}

// ============================================================================
// K_B fused: normalize + dropout (JIT threefry) + attn write + PV.
// CTA: 128 q-rows x 64 d out. grid (qt=8, bh=128).  (R8 structure)
// ============================================================================
#define PVS 68
#define PVV 72
#define PV_SMEM_FLOATS (128 * PVS + 2 * 64 * PVV + 128)
#define PV_SMEM_BYTES (PV_SMEM_FLOATS * 4)

extern "C" __global__ void __launch_bounds__(256)
pv_kernel(float* __restrict__ Attn, const float* __restrict__ V,
          float* __restrict__ Out, uint32_t rk0, uint32_t rk1)
{
    extern __shared__ float sm[];
    float*    sP   = sm;                                   // 128*68
    uint32_t* sVh  = (uint32_t*)(sm + 128 * PVS);          // 64*72
    float*    sVl  = (float*)(sVh + 64 * PVV);             // 64*72
    float*    sInv = sVl + 64 * PVV;                       // 128

    const int qt = blockIdx.x, bh = blockIdx.y;
    const int tid = threadIdx.x;
    const int w = tid >> 5, lane = tid & 31, g = lane >> 2, tig = lane & 3;

    float* Ag = Attn + ((size_t)bh * Ss + qt * 128) * Ss;
    const float* Vg = V + (size_t)bh * Ss * Dd;

    // deterministic row-sum reduction from qk partials (16 per row)
    if (tid < 128) {
        const float4* p = (const float4*)(g_rowsum +
            ((size_t)(bh * Ss + qt * 128 + tid)) * 16);
        float s = 0.f;
        #pragma unroll
        for (int jj = 0; jj < 4; ++jj) {
            float4 v = p[jj];
            s += (v.x + v.y) + (v.z + v.w);
        }
        sInv[tid] = (1.0f / 0.9f) / s;
    }

    float acc[8][4];
    #pragma unroll
    for (int nt = 0; nt < 8; ++nt)
        #pragma unroll
        for (int jj = 0; jj < 4; ++jj) acc[nt][jj] = 0.f;

    const uint32_t rowg_base = (uint32_t)(bh * Ss + qt * 128);

    for (int kt = 0; kt < 16; ++kt) {
        __syncthreads();
        // load e tile -> w = keep ? e*inv : 0 -> attn gmem + sP
        for (int i = tid; i < 128 * 16; i += 256) {
            int row = i >> 4, c4 = (i & 15) * 4;
            float* gp = Ag + (size_t)row * Ss + kt * 64 + c4;
            float4 v = *(const float4*)gp;
            const float inv = sInv[row];
            const uint32_t idx0 = ((rowg_base + row) << 10) + kt * 64 + c4;
            uint32_t b0 = jax_bits(idx0 + 0, rk0, rk1);
            uint32_t b1 = jax_bits(idx0 + 1, rk0, rk1);
            uint32_t b2 = jax_bits(idx0 + 2, rk0, rk1);
            uint32_t b3 = jax_bits(idx0 + 3, rk0, rk1);
            v.x = (b0 < KEEP_THRESH) ? v.x * inv : 0.f;
            v.y = (b1 < KEEP_THRESH) ? v.y * inv : 0.f;
            v.z = (b2 < KEEP_THRESH) ? v.z * inv : 0.f;
            v.w = (b3 < KEEP_THRESH) ? v.w * inv : 0.f;
            *(float4*)gp = v;
            float* p = sP + row * PVS + c4;
            p[0] = v.x; p[1] = v.y; p[2] = v.z; p[3] = v.w;
        }
        // load V tile, hi/lo presplit
        for (int i = tid; i < 64 * 16; i += 256) {
            int row = i >> 4, c4 = (i & 15) * 4;
            float4 v = ((const float4*)(Vg + (size_t)(kt * 64 + row) * Dd))[(i & 15)];
            uint32_t* ph = sVh + row * PVV + c4;
            float*    pl = sVl + row * PVV + c4;
            uint32_t h0 = f2tf(v.x), h1 = f2tf(v.y), h2 = f2tf(v.z), h3 = f2tf(v.w);
            ph[0] = h0; ph[1] = h1; ph[2] = h2; ph[3] = h3;
            pl[0] = v.x - __uint_as_float(h0); pl[1] = v.y - __uint_as_float(h1);
            pl[2] = v.z - __uint_as_float(h2); pl[3] = v.w - __uint_as_float(h3);
        }
        __syncthreads();

        #pragma unroll
        for (int ks = 0; ks < 8; ++ks) {
            const int c = ks * 8 + tig;
            float v0 = sP[(w * 16 + g) * PVS + c];
            float v1 = sP[(w * 16 + g + 8) * PVS + c];
            float v2 = sP[(w * 16 + g) * PVS + c + 4];
            float v3 = sP[(w * 16 + g + 8) * PVS + c + 4];
            uint32_t A0h = f2tf(v0), A1h = f2tf(v1), A2h = f2tf(v2), A3h = f2tf(v3);
            uint32_t A0l = __float_as_uint(v0 - __uint_as_float(A0h));
            uint32_t A1l = __float_as_uint(v1 - __uint_as_float(A1h));
            uint32_t A2l = __float_as_uint(v2 - __uint_as_float(A2h));
            uint32_t A3l = __float_as_uint(v3 - __uint_as_float(A3h));

            #pragma unroll
            for (int nt = 0; nt < 8; ++nt) {
                const int col = nt * 8 + g;
                uint32_t bh0 = sVh[(ks * 8 + tig) * PVV + col];
                uint32_t bh1 = sVh[(ks * 8 + tig + 4) * PVV + col];
                uint32_t bl0 = __float_as_uint(sVl[(ks * 8 + tig) * PVV + col]);
                uint32_t bl1 = __float_as_uint(sVl[(ks * 8 + tig + 4) * PVV + col]);
                MMA_TF32(acc[nt][0],acc[nt][1],acc[nt][2],acc[nt][3],
                         A0h,A1h,A2h,A3h, bh0,bh1);
                MMA_TF32(acc[nt][0],acc[nt][1],acc[nt][2],acc[nt][3],
                         A0h,A1h,A2h,A3h, bl0,bl1);
                MMA_TF32(acc[nt][0],acc[nt][1],acc[nt][2],acc[nt][3],
                         A0l,A1l,A2l,A3l, bh0,bh1);
            }
        }
    }

    const int gr0 = qt * 128 + w * 16 + g;
    const int gr1 = gr0 + 8;
    float* Ob = Out + (size_t)bh * Ss * Dd;
    #pragma unroll
    for (int nt = 0; nt < 8; ++nt) {
        const int col = nt * 8 + tig * 2;
        *(float2*)(Ob + (size_t)gr0 * Dd + col) = make_float2(acc[nt][0], acc[nt][1]);
        *(float2*)(Ob + (size_t)gr1 * Dd + col) = make_float2(acc[nt][2], acc[nt][3]);
    }
}

// ============================================================================
extern "C" void kernel_launch(void* const* d_in, const int* in_sizes, int n_in,
                              void* d_out, int out_size) {
    const float* Q = (const float*)d_in[0];
    const float* K = (const float*)d_in[1];
    const float* V = (const float*)d_in[2];
    const int*   M = (const int*)d_in[3];

    float* out  = (float*)d_out;
    float* attn = out + (size_t)Bb * Hh * Ss * Dd;

    constexpr K2 DK = threefry_host(0u, 42u, 0u, 7u);

    cudaFuncSetAttribute(qk_kernel, cudaFuncAttributeMaxDynamicSharedMemorySize,
                         QK_SMEM_BYTES);
    cudaFuncSetAttribute(pv_kernel, cudaFuncAttributeMaxDynamicSharedMemorySize,
                         PV_SMEM_BYTES);

    qk_kernel<<<dim3(16, 8, 128), 256, QK_SMEM_BYTES>>>(Q, K, M, attn);
    pv_kernel<<<dim3(8, 128), 256, PV_SMEM_BYTES>>>(attn, V, out, DK.a, DK.b);
}